// round 16
// baseline (speedup 1.0000x reference)
#include <cuda_runtime.h>
#include <cuda_fp16.h>
#include <cstdint>

#define B_SZ 8192
#define L_SZ 64
#define EMB  64
#define HID  128
#define G3   384
#define OUTD 128
#define NVAL 1000

__device__ float g_tab[NVAL * G3];          // xg table, PERMUTED within 16-chunks (L2-hot)
__device__ uint32_t g_Bf[8 * 8 * 32 * 12];  // Whh fp16 B-fragments, 96KB
__device__ uint32_t g_Of[8 * 32 * 32];      // Wout fp16 B-fragments, 32KB

__device__ __forceinline__ float ftanh_fast(float x) {
    float r;
    asm("tanh.approx.f32 %0, %1;" : "=f"(r) : "f"(x));
    return r;
}
__device__ __forceinline__ float fsig_fast(float x) {
    return fmaf(0.5f, ftanh_fast(0.5f * x), 0.5f);
}
__device__ __forceinline__ uint32_t packh2(float lo, float hi) {
    __half2 h = __floats2half2_rn(lo, hi);
    return *reinterpret_cast<uint32_t*>(&h);
}
__device__ __forceinline__ void hmma(float* d, const uint32_t* a, uint32_t b0, uint32_t b1) {
    asm volatile("mma.sync.aligned.m16n8k16.row.col.f32.f16.f16.f32 "
        "{%0,%1,%2,%3}, {%4,%5,%6,%7}, {%8,%9}, {%0,%1,%2,%3};"
        : "+f"(d[0]), "+f"(d[1]), "+f"(d[2]), "+f"(d[3])
        : "r"(a[0]), "r"(a[1]), "r"(a[2]), "r"(a[3]), "r"(b0), "r"(b1));
}
__device__ __forceinline__ int pperm(int o) {
    return 4 * ((o & 7) >> 1) + (((o >> 3) & 1) << 1) + (o & 1);
}

// ---------------- fused prologue: fragment packing + xg table, one launch ----------------
// blocks [0,128): pack g_Bf / g_Of.  blocks [128,253): table, 8 v's per block.
__global__ __launch_bounds__(384) void prep_all(const float* __restrict__ Wih,
                                                const float* __restrict__ Whh,
                                                const float* __restrict__ bih,
                                                const float* __restrict__ bhh,
                                                const float* __restrict__ Wout,
                                                const float* __restrict__ embed) {
    const int b = blockIdx.x, tid = threadIdx.x;
    if (b < 128) {
        int i = b * 384 + tid;                 // 0..49151 == G3*HID exactly
        {   // Whh fragment: gj = i/HID, k = i%HID
            int gj = i >> 7, k = i & 127;
            uint16_t hb = __half_as_ushort(__float2half_rn(Whh[i]));
            int gate = gj >> 7, jr = gj & 127;
            int jc = jr >> 4, nt = (jr >> 3) & 1, nl = jr & 7;
            int kc = k >> 4, kk = k & 15;
            int breg = kk >> 3, q = (kk & 7) >> 1, hs = kk & 1;
            int T = nl * 4 + q, f = gate * 2 + nt;
            int u = ((jc * 8 + kc) * 32 + T) * 12 + f * 2 + breg;
            ((uint16_t*)g_Bf)[u * 2 + hs] = hb;
        }
        if (i < OUTD * HID) {                  // Wout fragment: o = i/HID, k = i%HID
            int o = i >> 7, k = i & 127;
            uint16_t hb = __half_as_ushort(__float2half_rn(Wout[i]));
            int f = o >> 3, nl = o & 7;
            int kc = k >> 4, kk = k & 15;
            int breg = kk >> 3, q = (kk & 7) >> 1, hs = kk & 1;
            int T = nl * 4 + q;
            int u = (kc * 32 + T) * 32 + f * 2 + breg;
            ((uint16_t*)g_Of)[u * 2 + hs] = hb;
        }
    } else {
        // table: tab[v][perm(gj)] = sum_k embed[v][k]*Wih[gj][k] + bih[gj] + (gj<256)*bhh[gj]
        __shared__ float es[8][EMB];
        const int v0 = (b - 128) * 8;
        for (int i = tid; i < 8 * EMB; i += 384)
            es[i >> 6][i & 63] = embed[(v0 + (i >> 6)) * EMB + (i & 63)];
        __syncthreads();
        const int gj = tid;
        float acc[8];
        #pragma unroll
        for (int v = 0; v < 8; v++) acc[v] = 0.0f;
        const float* wr = Wih + gj * EMB;
        #pragma unroll 8
        for (int k = 0; k < EMB; k++) {
            float wv = __ldg(wr + k);
            #pragma unroll
            for (int v = 0; v < 8; v++) acc[v] = fmaf(es[v][k], wv, acc[v]);
        }
        float cb = bih[gj] + (gj < 2 * HID ? bhh[gj] : 0.0f);
        const int gate = gj >> 7, rest = gj & 127, chunk = rest >> 4, o = rest & 15;
        const int dst = gate * 128 + chunk * 16 + pperm(o);
        #pragma unroll
        for (int v = 0; v < 8; v++)
            g_tab[(size_t)(v0 + v) * G3 + dst] = acc[v] + cb;
    }
}

// ---- GRU: R11 structure (pair N-split, 2 warps/SMSP) + peeled zero step t=0 ----
#define NTH 256
#define EXCH_U32 32896
#define GRU_SMEM ((EXCH_U32 + 2 * NTH * 16) * 4)   // 164352 bytes
__global__ __launch_bounds__(NTH, 1) void gru_kernel(const int* __restrict__ x,
                                                     const float* __restrict__ bhh,
                                                     const float* __restrict__ bout,
                                                     float* __restrict__ out) {
    extern __shared__ uint32_t sm[];
    uint32_t* Bs = sm;                      // 24576 u32 (96KB)
    uint32_t* Os = sm + 24576;              // 8192 u32 (32KB)
    float* bns = (float*)(sm + 32768);      // 128 floats, permuted bhh_n
    uint4* exch = (uint4*)(sm + EXCH_U32);  // 2 x 256 threads x 4 uint4
    const int tid = threadIdx.x;
    {
        uint4* d = (uint4*)sm;
        const uint4* s1 = (const uint4*)g_Bf;
        for (int i = tid; i < 6144; i += NTH) d[i] = s1[i];
        const uint4* s2 = (const uint4*)g_Of;
        for (int i = tid; i < 2048; i += NTH) d[6144 + i] = s2[i];
    }
    if (tid < 128) {
        int o = tid & 15, chunk = tid >> 4;
        bns[chunk * 16 + pperm(o)] = bhh[256 + tid];
    }
    __syncthreads();

    const int w = tid >> 5, T = tid & 31;
    const int sub = w & 1, pairid = w >> 1;
    const int g = T >> 2, a4 = (T & 3) * 4;
    const int rowA = blockIdx.x * 64 + pairid * 16 + g;
    const int rowB = rowA + 8;
    const int jbase = sub * 64;
    const float* __restrict__ tab = g_tab;
    const float* bnsw = bns + jbase + a4;
    const uint32_t* Bsw = Bs + sub * 4 * 8 * 32 * 12;

    uint32_t A[32];
    float hp[32];
    #pragma unroll
    for (int i = 0; i < 32; i++) { A[i] = 0u; hp[i] = 0.0f; }

    int idxA = x[rowA * L_SZ], idxB = x[rowB * L_SZ];
    const float* tA = tab + (size_t)idxA * G3 + jbase + a4;
    const float* tB = tab + (size_t)idxB * G3 + jbase + a4;

    // ---- peeled t=0: h0 = 0 → gates from xg seeds only (bit-identical to MMA-of-zeros) ----
    {
        uint4 AnR[4];
        #pragma unroll
        for (int jci = 0; jci < 4; jci++) {
            const int jo = jci * 16;
            float4 vrA = __ldg((const float4*)(tA + jo));
            float4 vrB = __ldg((const float4*)(tB + jo));
            float4 vzA = __ldg((const float4*)(tA + 128 + jo));
            float4 vzB = __ldg((const float4*)(tB + 128 + jo));
            float4 vnA = __ldg((const float4*)(tA + 256 + jo));
            float4 vnB = __ldg((const float4*)(tB + 256 + jo));
            float4 bn4 = *(const float4*)(bnsw + jo);
            float xr[8] = {vrA.x, vrA.y, vrB.x, vrB.y, vrA.z, vrA.w, vrB.z, vrB.w};
            float xz[8] = {vzA.x, vzA.y, vzB.x, vzB.y, vzA.z, vzA.w, vzB.z, vzB.w};
            float xn[8] = {vnA.x, vnA.y, vnB.x, vnB.y, vnA.z, vnA.w, vnB.z, vnB.w};
            float bn[8] = {bn4.x, bn4.y, bn4.x, bn4.y, bn4.z, bn4.w, bn4.z, bn4.w};
            float hv[8];
            #pragma unroll
            for (int u = 0; u < 8; u++) {
                float r = fsig_fast(xr[u]);
                float z = fsig_fast(xz[u]);
                float n = ftanh_fast(fmaf(r, bn[u], xn[u]));
                float h = fmaf(z, hp[jci * 8 + u] - n, n);
                hp[jci * 8 + u] = h;
                hv[u] = h;
            }
            AnR[jci] = make_uint4(packh2(hv[0], hv[1]), packh2(hv[2], hv[3]),
                                  packh2(hv[4], hv[5]), packh2(hv[6], hv[7]));
        }
        uint4* mine = exch + ((size_t)0 * NTH + tid) * 4;
        mine[0] = AnR[0]; mine[1] = AnR[1]; mine[2] = AnR[2]; mine[3] = AnR[3];
        asm volatile("bar.sync %0, 64;" :: "r"(1 + pairid) : "memory");
        const uint4* theirs = exch + ((size_t)0 * NTH + (tid ^ 32)) * 4;
        uint4 p0 = theirs[0], p1 = theirs[1], p2 = theirs[2], p3 = theirs[3];
        if (sub == 0) {
            A[0]=AnR[0].x; A[1]=AnR[0].y; A[2]=AnR[0].z; A[3]=AnR[0].w;
            A[4]=AnR[1].x; A[5]=AnR[1].y; A[6]=AnR[1].z; A[7]=AnR[1].w;
            A[8]=AnR[2].x; A[9]=AnR[2].y; A[10]=AnR[2].z; A[11]=AnR[2].w;
            A[12]=AnR[3].x; A[13]=AnR[3].y; A[14]=AnR[3].z; A[15]=AnR[3].w;
            A[16]=p0.x; A[17]=p0.y; A[18]=p0.z; A[19]=p0.w;
            A[20]=p1.x; A[21]=p1.y; A[22]=p1.z; A[23]=p1.w;
            A[24]=p2.x; A[25]=p2.y; A[26]=p2.z; A[27]=p2.w;
            A[28]=p3.x; A[29]=p3.y; A[30]=p3.z; A[31]=p3.w;
        } else {
            A[0]=p0.x; A[1]=p0.y; A[2]=p0.z; A[3]=p0.w;
            A[4]=p1.x; A[5]=p1.y; A[6]=p1.z; A[7]=p1.w;
            A[8]=p2.x; A[9]=p2.y; A[10]=p2.z; A[11]=p2.w;
            A[12]=p3.x; A[13]=p3.y; A[14]=p3.z; A[15]=p3.w;
            A[16]=AnR[0].x; A[17]=AnR[0].y; A[18]=AnR[0].z; A[19]=AnR[0].w;
            A[20]=AnR[1].x; A[21]=AnR[1].y; A[22]=AnR[1].z; A[23]=AnR[1].w;
            A[24]=AnR[2].x; A[25]=AnR[2].y; A[26]=AnR[2].z; A[27]=AnR[2].w;
            A[28]=AnR[3].x; A[29]=AnR[3].y; A[30]=AnR[3].z; A[31]=AnR[3].w;
        }
        idxA = x[rowA * L_SZ + 1];
        idxB = x[rowB * L_SZ + 1];
        tA = tab + (size_t)idxA * G3 + jbase + a4;
        tB = tab + (size_t)idxB * G3 + jbase + a4;
    }

    // preload chunk 0 of step 1
    float4 crA = __ldg((const float4*)(tA));
    float4 crB = __ldg((const float4*)(tB));
    float4 czA = __ldg((const float4*)(tA + 128));
    float4 czB = __ldg((const float4*)(tB + 128));
    float4 cnA = __ldg((const float4*)(tA + 256));
    float4 cnB = __ldg((const float4*)(tB + 256));

    #pragma unroll 1
    for (int t = 1; t < L_SZ; t++) {
        int idxA2 = idxA, idxB2 = idxB;
        if (t + 1 < L_SZ) {
            idxA2 = x[rowA * L_SZ + t + 1];
            idxB2 = x[rowB * L_SZ + t + 1];
        }
        uint4 AnR[4];
        #pragma unroll
        for (int jci = 0; jci < 4; jci++) {
            float4 bn4 = *(const float4*)(bnsw + jci * 16);
            float d[6][4] = {
                {crA.x, crA.y, crB.x, crB.y}, {crA.z, crA.w, crB.z, crB.w},
                {czA.x, czA.y, czB.x, czB.y}, {czA.z, czA.w, czB.z, czB.w},
                {bn4.x, bn4.y, bn4.x, bn4.y}, {bn4.z, bn4.w, bn4.z, bn4.w}
            };
            float4 xnc_A = cnA, xnc_B = cnB;
            if (jci < 3) {
                const int jn = (jci + 1) * 16;
                crA = __ldg((const float4*)(tA + jn));
                crB = __ldg((const float4*)(tB + jn));
                czA = __ldg((const float4*)(tA + 128 + jn));
                czB = __ldg((const float4*)(tB + 128 + jn));
                cnA = __ldg((const float4*)(tA + 256 + jn));
                cnB = __ldg((const float4*)(tB + 256 + jn));
            } else {
                tA = tab + (size_t)idxA2 * G3 + jbase + a4;
                tB = tab + (size_t)idxB2 * G3 + jbase + a4;
                crA = __ldg((const float4*)(tA));
                crB = __ldg((const float4*)(tB));
                czA = __ldg((const float4*)(tA + 128));
                czB = __ldg((const float4*)(tB + 128));
                cnA = __ldg((const float4*)(tA + 256));
                cnB = __ldg((const float4*)(tB + 256));
            }

            #pragma unroll
            for (int kc = 0; kc < 8; kc++) {
                const uint4* bp = (const uint4*)(Bsw + ((jci * 8 + kc) * 32 + T) * 12);
                uint4 b0 = bp[0], b1 = bp[1], b2 = bp[2];
                hmma(d[0], &A[kc * 4], b0.x, b0.y);
                hmma(d[1], &A[kc * 4], b0.z, b0.w);
                hmma(d[2], &A[kc * 4], b1.x, b1.y);
                hmma(d[3], &A[kc * 4], b1.z, b1.w);
                hmma(d[4], &A[kc * 4], b2.x, b2.y);
                hmma(d[5], &A[kc * 4], b2.z, b2.w);
            }

            float xn[8] = {xnc_A.x, xnc_A.y, xnc_B.x, xnc_B.y,
                           xnc_A.z, xnc_A.w, xnc_B.z, xnc_B.w};
            float hv[8];
            #pragma unroll
            for (int u = 0; u < 8; u++) {
                int nt = u >> 2, pos = u & 3;
                float r = fsig_fast(d[nt][pos]);
                float z = fsig_fast(d[2 + nt][pos]);
                float n = ftanh_fast(fmaf(r, d[4 + nt][pos], xn[u]));
                float h = fmaf(z, hp[jci * 8 + u] - n, n);
                hp[jci * 8 + u] = h;
                hv[u] = h;
            }
            AnR[jci] = make_uint4(packh2(hv[0], hv[1]), packh2(hv[2], hv[3]),
                                  packh2(hv[4], hv[5]), packh2(hv[6], hv[7]));
        }

        {
            uint4* mine = exch + ((size_t)(t & 1) * NTH + tid) * 4;
            mine[0] = AnR[0]; mine[1] = AnR[1]; mine[2] = AnR[2]; mine[3] = AnR[3];
            asm volatile("bar.sync %0, 64;" :: "r"(1 + pairid) : "memory");
            const uint4* theirs = exch + ((size_t)(t & 1) * NTH + (tid ^ 32)) * 4;
            uint4 p0 = theirs[0], p1 = theirs[1], p2 = theirs[2], p3 = theirs[3];
            if (sub == 0) {
                A[0]=AnR[0].x; A[1]=AnR[0].y; A[2]=AnR[0].z; A[3]=AnR[0].w;
                A[4]=AnR[1].x; A[5]=AnR[1].y; A[6]=AnR[1].z; A[7]=AnR[1].w;
                A[8]=AnR[2].x; A[9]=AnR[2].y; A[10]=AnR[2].z; A[11]=AnR[2].w;
                A[12]=AnR[3].x; A[13]=AnR[3].y; A[14]=AnR[3].z; A[15]=AnR[3].w;
                A[16]=p0.x; A[17]=p0.y; A[18]=p0.z; A[19]=p0.w;
                A[20]=p1.x; A[21]=p1.y; A[22]=p1.z; A[23]=p1.w;
                A[24]=p2.x; A[25]=p2.y; A[26]=p2.z; A[27]=p2.w;
                A[28]=p3.x; A[29]=p3.y; A[30]=p3.z; A[31]=p3.w;
            } else {
                A[0]=p0.x; A[1]=p0.y; A[2]=p0.z; A[3]=p0.w;
                A[4]=p1.x; A[5]=p1.y; A[6]=p1.z; A[7]=p1.w;
                A[8]=p2.x; A[9]=p2.y; A[10]=p2.z; A[11]=p2.w;
                A[12]=p3.x; A[13]=p3.y; A[14]=p3.z; A[15]=p3.w;
                A[16]=AnR[0].x; A[17]=AnR[0].y; A[18]=AnR[0].z; A[19]=AnR[0].w;
                A[20]=AnR[1].x; A[21]=AnR[1].y; A[22]=AnR[1].z; A[23]=AnR[1].w;
                A[24]=AnR[2].x; A[25]=AnR[2].y; A[26]=AnR[2].z; A[27]=AnR[2].w;
                A[28]=AnR[3].x; A[29]=AnR[3].y; A[30]=AnR[3].z; A[31]=AnR[3].w;
            }
        }
        idxA = idxA2; idxB = idxB2;
    }

    // output projection: out = h @ Wout^T + bout
    float od[8][4];
    #pragma unroll
    for (int f = 0; f < 8; f++)
        #pragma unroll
        for (int p = 0; p < 4; p++) od[f][p] = 0.0f;
    #pragma unroll
    for (int kc = 0; kc < 8; kc++) {
        const uint4* op = (const uint4*)(Os + (kc * 32 + T) * 32) + sub * 4;
        #pragma unroll
        for (int f2 = 0; f2 < 4; f2++) {
            uint4 v = op[f2];
            hmma(od[f2 * 2 + 0], &A[kc * 4], v.x, v.y);
            hmma(od[f2 * 2 + 1], &A[kc * 4], v.z, v.w);
        }
    }
    const int q2 = (T & 3) * 2;
    #pragma unroll
    for (int f2 = 0; f2 < 8; f2++) {
        const int f = sub * 8 + f2;
        float2 bo = *(const float2*)(bout + f * 8 + q2);
        float2 oA = make_float2(od[f2][0] + bo.x, od[f2][1] + bo.y);
        float2 oB = make_float2(od[f2][2] + bo.x, od[f2][3] + bo.y);
        *(float2*)(out + (size_t)rowA * OUTD + f * 8 + q2) = oA;
        *(float2*)(out + (size_t)rowB * OUTD + f * 8 + q2) = oB;
    }
}

extern "C" void kernel_launch(void* const* d_in, const int* in_sizes, int n_in,
                              void* d_out, int out_size) {
    const int*   x     = (const int*)d_in[0];
    const float* embed = (const float*)d_in[1];
    const float* Wih   = (const float*)d_in[2];
    const float* Whh   = (const float*)d_in[3];
    const float* bih   = (const float*)d_in[4];
    const float* bhh   = (const float*)d_in[5];
    const float* Wout  = (const float*)d_in[6];
    const float* bout  = (const float*)d_in[7];
    float* out = (float*)d_out;

    static bool attr_done = false;
    if (!attr_done) {
        cudaFuncSetAttribute(gru_kernel, cudaFuncAttributeMaxDynamicSharedMemorySize, GRU_SMEM);
        attr_done = true;
    }

    prep_all<<<128 + NVAL / 8, 384>>>(Wih, Whh, bih, bhh, Wout, embed);
    gru_kernel<<<B_SZ / 64, NTH, GRU_SMEM>>>(x, bhh, bout, out);
}

// round 17
// speedup vs baseline: 1.2475x; 1.2475x over previous
#include <cuda_runtime.h>
#include <cuda_fp16.h>
#include <cstdint>

#define B_SZ 8192
#define L_SZ 64
#define EMB  64
#define HID  128
#define G3   384
#define OUTD 128
#define NVAL 1000

__device__ float g_tab[NVAL * G3];          // xg table, PERMUTED within 16-chunks (L2-hot)
__device__ float g_Wih_t[EMB * G3];
__device__ float g_cbias[G3];
__device__ uint32_t g_Bf[8 * 8 * 32 * 12];  // Whh fp16 B-fragments, 96KB
__device__ uint32_t g_Of[8 * 32 * 32];      // Wout fp16 B-fragments, 32KB

__device__ __forceinline__ float ftanh_fast(float x) {
    float r;
    asm("tanh.approx.f32 %0, %1;" : "=f"(r) : "f"(x));
    return r;
}
__device__ __forceinline__ float fsig_fast(float x) {
    return fmaf(0.5f, ftanh_fast(0.5f * x), 0.5f);
}
__device__ __forceinline__ uint32_t packh2(float lo, float hi) {
    __half2 h = __floats2half2_rn(lo, hi);
    return *reinterpret_cast<uint32_t*>(&h);
}
__device__ __forceinline__ void hmma(float* d, const uint32_t* a, uint32_t b0, uint32_t b1) {
    asm volatile("mma.sync.aligned.m16n8k16.row.col.f32.f16.f16.f32 "
        "{%0,%1,%2,%3}, {%4,%5,%6,%7}, {%8,%9}, {%0,%1,%2,%3};"
        : "+f"(d[0]), "+f"(d[1]), "+f"(d[2]), "+f"(d[3])
        : "r"(a[0]), "r"(a[1]), "r"(a[2]), "r"(a[3]), "r"(b0), "r"(b1));
}
__device__ __forceinline__ int pperm(int o) {
    return 4 * ((o & 7) >> 1) + (((o >> 3) & 1) << 1) + (o & 1);
}

// ---------------- prep (split form — fused version measured 3x slower) ----------------
__global__ void prep_kernel(const float* __restrict__ Wih, const float* __restrict__ Whh,
                            const float* __restrict__ bih, const float* __restrict__ bhh,
                            const float* __restrict__ Wout) {
    int i = blockIdx.x * blockDim.x + threadIdx.x;
    if (i < EMB * G3) { int k = i / G3, gj = i % G3; g_Wih_t[i] = Wih[gj * EMB + k]; }
    if (i < G3) g_cbias[i] = bih[i] + (i < 2 * HID ? bhh[i] : 0.0f);
    if (i < G3 * HID) {
        int gj = i / HID, k = i % HID;
        uint16_t hb = __half_as_ushort(__float2half_rn(Whh[i]));
        int gate = gj >> 7, jr = gj & 127;
        int jc = jr >> 4, nt = (jr >> 3) & 1, nl = jr & 7;
        int kc = k >> 4, kk = k & 15;
        int breg = kk >> 3, q = (kk & 7) >> 1, hs = kk & 1;
        int T = nl * 4 + q, f = gate * 2 + nt;
        int u = ((jc * 8 + kc) * 32 + T) * 12 + f * 2 + breg;
        ((uint16_t*)g_Bf)[u * 2 + hs] = hb;
    }
    if (i < OUTD * HID) {
        int o = i / HID, k = i % HID;
        uint16_t hb = __half_as_ushort(__float2half_rn(Wout[i]));
        int f = o >> 3, nl = o & 7;
        int kc = k >> 4, kk = k & 15;
        int breg = kk >> 3, q = (kk & 7) >> 1, hs = kk & 1;
        int T = nl * 4 + q;
        int u = (kc * 32 + T) * 32 + f * 2 + breg;
        ((uint16_t*)g_Of)[u * 2 + hs] = hb;
    }
}

__global__ void table_kernel(const float* __restrict__ embed) {
    __shared__ float es[EMB];
    const int v = blockIdx.x, gj = threadIdx.x;
    if (gj < EMB) es[gj] = embed[v * EMB + gj];
    __syncthreads();
    float acc = 0.0f;
    #pragma unroll 8
    for (int k = 0; k < EMB; k++) acc = fmaf(es[k], g_Wih_t[k * G3 + gj], acc);
    const int gate = gj >> 7, rest = gj & 127, chunk = rest >> 4, o = rest & 15;
    g_tab[v * G3 + gate * 128 + chunk * 16 + pperm(o)] = acc + g_cbias[gj];
}

// ---- GRU: 2 M-tiles per B-fragment load (L1 traffic halved), 4-way j-split quads ----
#define NTH 256
#define EXCH_U32 32896
#define GRU_SMEM ((EXCH_U32 + 8192) * 4)   // 164352 bytes
__global__ __launch_bounds__(NTH, 1) void gru_kernel(const int* __restrict__ x,
                                                     const float* __restrict__ bhh,
                                                     const float* __restrict__ bout,
                                                     float* __restrict__ out) {
    extern __shared__ uint32_t sm[];
    uint32_t* Bs = sm;                      // 24576 u32 (96KB)
    uint32_t* Os = sm + 24576;              // 8192 u32 (32KB)
    float* bns = (float*)(sm + 32768);      // 128 floats, permuted bhh_n
    uint4* exch = (uint4*)(sm + EXCH_U32);  // [(parity*2+quad)*16 + tile*8 + jc][lane]
    const int tid = threadIdx.x;
    {
        uint4* d = (uint4*)sm;
        const uint4* s1 = (const uint4*)g_Bf;
        for (int i = tid; i < 6144; i += NTH) d[i] = s1[i];
        const uint4* s2 = (const uint4*)g_Of;
        for (int i = tid; i < 2048; i += NTH) d[6144 + i] = s2[i];
    }
    if (tid < 128) {
        int o = tid & 15, chunk = tid >> 4;
        bns[chunk * 16 + pperm(o)] = bhh[256 + tid];
    }
    __syncthreads();

    const int w = tid >> 5, T = tid & 31;
    const int sub = w & 3, quad = w >> 2;      // quad (4 warps) owns 32 rows = 2 M-tiles
    const int g = T >> 2, a4 = (T & 3) * 4;
    const int base = blockIdx.x * 64 + quad * 32;
    const int rA0 = base + g, rB0 = base + 8 + g;
    const int rA1 = base + 16 + g, rB1 = base + 24 + g;
    const int jbase = sub * 32;                // own j range: 2 chunks
    const float* __restrict__ tab = g_tab;
    const float* bnsw = bns + jbase + a4;
    const uint32_t* Bsw = Bs + sub * 2 * (8 * 32 * 12);
    uint4* const exq = exch + quad * 16 * 32 + T;   // quad slice, lane fixed

    uint32_t A0[32], A1[32];
    float hp0[16], hp1[16];
    #pragma unroll
    for (int i = 0; i < 32; i++) { A0[i] = 0u; A1[i] = 0u; }
    #pragma unroll
    for (int i = 0; i < 16; i++) { hp0[i] = 0.0f; hp1[i] = 0.0f; }

    int iA0 = x[rA0 * L_SZ], iB0 = x[rB0 * L_SZ];
    int iA1 = x[rA1 * L_SZ], iB1 = x[rB1 * L_SZ];

// gate epilogue from MMA accumulators (xr/xz pre-seeded in D)
#define EPI(D, XNA, XNB, HP, OFF, AN) do {                                       \
    float xn_[8] = {XNA.x, XNA.y, XNB.x, XNB.y, XNA.z, XNA.w, XNB.z, XNB.w};     \
    float hv_[8];                                                                \
    _Pragma("unroll")                                                            \
    for (int u = 0; u < 8; u++) {                                                \
        int nt = u >> 2, pos = u & 3;                                            \
        float r = fsig_fast(D[nt][pos]);                                         \
        float z = fsig_fast(D[2 + nt][pos]);                                     \
        float n = ftanh_fast(fmaf(r, D[4 + nt][pos], xn_[u]));                   \
        float h = fmaf(z, HP[(OFF) + u] - n, n);                                 \
        HP[(OFF) + u] = h;                                                       \
        hv_[u] = h;                                                              \
    }                                                                            \
    AN = make_uint4(packh2(hv_[0], hv_[1]), packh2(hv_[2], hv_[3]),              \
                    packh2(hv_[4], hv_[5]), packh2(hv_[6], hv_[7]));             \
} while (0)

// load A fragments for both tiles from exchange, parity P
#define LOAD_A(P) do {                                                           \
    _Pragma("unroll")                                                            \
    for (int c = 0; c < 8; c++) {                                                \
        uint4 v0 = exq[(((P) * 32) + c) * 32];                                   \
        A0[c * 4 + 0] = v0.x; A0[c * 4 + 1] = v0.y;                              \
        A0[c * 4 + 2] = v0.z; A0[c * 4 + 3] = v0.w;                              \
        uint4 v1 = exq[(((P) * 32) + 8 + c) * 32];                               \
        A1[c * 4 + 0] = v1.x; A1[c * 4 + 1] = v1.y;                              \
        A1[c * 4 + 2] = v1.z; A1[c * 4 + 3] = v1.w;                              \
    }                                                                            \
} while (0)

    // ---- peeled t=0: h0=0 → gates from seeds only ----
    {
        #pragma unroll
        for (int jcl = 0; jcl < 2; jcl++) {
            const int jo = jcl * 16;
            const int jc = sub * 2 + jcl;
            float4 bn4 = *(const float4*)(bnsw + jo);
            const float* tA0 = tab + (size_t)iA0 * G3 + jbase + a4 + jo;
            const float* tB0 = tab + (size_t)iB0 * G3 + jbase + a4 + jo;
            const float* tA1 = tab + (size_t)iA1 * G3 + jbase + a4 + jo;
            const float* tB1 = tab + (size_t)iB1 * G3 + jbase + a4 + jo;
            #pragma unroll
            for (int tile = 0; tile < 2; tile++) {
                const float* pA = tile ? tA1 : tA0;
                const float* pB = tile ? tB1 : tB0;
                float* hp = tile ? hp1 : hp0;
                float4 vr_A = __ldg((const float4*)(pA));
                float4 vr_B = __ldg((const float4*)(pB));
                float4 vz_A = __ldg((const float4*)(pA + 128));
                float4 vz_B = __ldg((const float4*)(pB + 128));
                float4 vn_A = __ldg((const float4*)(pA + 256));
                float4 vn_B = __ldg((const float4*)(pB + 256));
                float xr[8] = {vr_A.x, vr_A.y, vr_B.x, vr_B.y, vr_A.z, vr_A.w, vr_B.z, vr_B.w};
                float xz[8] = {vz_A.x, vz_A.y, vz_B.x, vz_B.y, vz_A.z, vz_A.w, vz_B.z, vz_B.w};
                float xn[8] = {vn_A.x, vn_A.y, vn_B.x, vn_B.y, vn_A.z, vn_A.w, vn_B.z, vn_B.w};
                float bn[8] = {bn4.x, bn4.y, bn4.x, bn4.y, bn4.z, bn4.w, bn4.z, bn4.w};
                float hv[8];
                #pragma unroll
                for (int u = 0; u < 8; u++) {
                    float r = fsig_fast(xr[u]);
                    float z = fsig_fast(xz[u]);
                    float n = ftanh_fast(fmaf(r, bn[u], xn[u]));
                    float h = fmaf(z, hp[jcl * 8 + u] - n, n);
                    hp[jcl * 8 + u] = h;
                    hv[u] = h;
                }
                exq[(tile * 8 + jc) * 32] =
                    make_uint4(packh2(hv[0], hv[1]), packh2(hv[2], hv[3]),
                               packh2(hv[4], hv[5]), packh2(hv[6], hv[7]));
            }
        }
        asm volatile("bar.sync %0, 128;" :: "r"(1 + quad) : "memory");
        LOAD_A(0);
        iA0 = x[rA0 * L_SZ + 1]; iB0 = x[rB0 * L_SZ + 1];
        iA1 = x[rA1 * L_SZ + 1]; iB1 = x[rB1 * L_SZ + 1];
    }

    const float* tA0 = tab + (size_t)iA0 * G3 + jbase + a4;
    const float* tB0 = tab + (size_t)iB0 * G3 + jbase + a4;
    const float* tA1 = tab + (size_t)iA1 * G3 + jbase + a4;
    const float* tB1 = tab + (size_t)iB1 * G3 + jbase + a4;

    // preload chunk jcl=0 of step 1 (12 float4)
    float4 crA0 = __ldg((const float4*)(tA0)),       crB0 = __ldg((const float4*)(tB0));
    float4 czA0 = __ldg((const float4*)(tA0 + 128)), czB0 = __ldg((const float4*)(tB0 + 128));
    float4 cnA0 = __ldg((const float4*)(tA0 + 256)), cnB0 = __ldg((const float4*)(tB0 + 256));
    float4 crA1 = __ldg((const float4*)(tA1)),       crB1 = __ldg((const float4*)(tB1));
    float4 czA1 = __ldg((const float4*)(tA1 + 128)), czB1 = __ldg((const float4*)(tB1 + 128));
    float4 cnA1 = __ldg((const float4*)(tA1 + 256)), cnB1 = __ldg((const float4*)(tB1 + 256));

    #pragma unroll 1
    for (int t = 1; t < L_SZ; t++) {
        int jA0 = iA0, jB0 = iB0, jA1 = iA1, jB1 = iB1;
        if (t + 1 < L_SZ) {
            jA0 = x[rA0 * L_SZ + t + 1]; jB0 = x[rB0 * L_SZ + t + 1];
            jA1 = x[rA1 * L_SZ + t + 1]; jB1 = x[rB1 * L_SZ + t + 1];
        }
        const int p = t & 1;
        #pragma unroll
        for (int jcl = 0; jcl < 2; jcl++) {
            const int jc = sub * 2 + jcl;
            float4 bn4 = *(const float4*)(bnsw + jcl * 16);
            // D seeded with xr/xz/bhh_n
            float d0[6][4] = {
                {crA0.x, crA0.y, crB0.x, crB0.y}, {crA0.z, crA0.w, crB0.z, crB0.w},
                {czA0.x, czA0.y, czB0.x, czB0.y}, {czA0.z, czA0.w, czB0.z, czB0.w},
                {bn4.x, bn4.y, bn4.x, bn4.y},     {bn4.z, bn4.w, bn4.z, bn4.w}
            };
            float d1[6][4] = {
                {crA1.x, crA1.y, crB1.x, crB1.y}, {crA1.z, crA1.w, crB1.z, crB1.w},
                {czA1.x, czA1.y, czB1.x, czB1.y}, {czA1.z, czA1.w, czB1.z, czB1.w},
                {bn4.x, bn4.y, bn4.x, bn4.y},     {bn4.z, bn4.w, bn4.z, bn4.w}
            };
            float4 xnA0 = cnA0, xnB0 = cnB0, xnA1 = cnA1, xnB1 = cnB1;

            // prefetch next chunk (wraps into next step)
            if (jcl == 0) {
                crA0 = __ldg((const float4*)(tA0 + 16));
                crB0 = __ldg((const float4*)(tB0 + 16));
                czA0 = __ldg((const float4*)(tA0 + 144));
                czB0 = __ldg((const float4*)(tB0 + 144));
                cnA0 = __ldg((const float4*)(tA0 + 272));
                cnB0 = __ldg((const float4*)(tB0 + 272));
                crA1 = __ldg((const float4*)(tA1 + 16));
                crB1 = __ldg((const float4*)(tB1 + 16));
                czA1 = __ldg((const float4*)(tA1 + 144));
                czB1 = __ldg((const float4*)(tB1 + 144));
                cnA1 = __ldg((const float4*)(tA1 + 272));
                cnB1 = __ldg((const float4*)(tB1 + 272));
            } else {
                tA0 = tab + (size_t)jA0 * G3 + jbase + a4;
                tB0 = tab + (size_t)jB0 * G3 + jbase + a4;
                tA1 = tab + (size_t)jA1 * G3 + jbase + a4;
                tB1 = tab + (size_t)jB1 * G3 + jbase + a4;
                crA0 = __ldg((const float4*)(tA0));
                crB0 = __ldg((const float4*)(tB0));
                czA0 = __ldg((const float4*)(tA0 + 128));
                czB0 = __ldg((const float4*)(tB0 + 128));
                cnA0 = __ldg((const float4*)(tA0 + 256));
                cnB0 = __ldg((const float4*)(tB0 + 256));
                crA1 = __ldg((const float4*)(tA1));
                crB1 = __ldg((const float4*)(tB1));
                czA1 = __ldg((const float4*)(tA1 + 128));
                czB1 = __ldg((const float4*)(tB1 + 128));
                cnA1 = __ldg((const float4*)(tA1 + 256));
                cnB1 = __ldg((const float4*)(tB1 + 256));
            }

            // 8 k-chunks: 3 LDS.128 feed 12 HMMA (2 tiles)
            #pragma unroll
            for (int kc = 0; kc < 8; kc++) {
                const uint4* bp = (const uint4*)(Bsw + ((jcl * 8 + kc) * 32 + T) * 12);
                uint4 b0 = bp[0], b1 = bp[1], b2 = bp[2];
                hmma(d0[0], &A0[kc * 4], b0.x, b0.y);
                hmma(d0[1], &A0[kc * 4], b0.z, b0.w);
                hmma(d0[2], &A0[kc * 4], b1.x, b1.y);
                hmma(d0[3], &A0[kc * 4], b1.z, b1.w);
                hmma(d0[4], &A0[kc * 4], b2.x, b2.y);
                hmma(d0[5], &A0[kc * 4], b2.z, b2.w);
                hmma(d1[0], &A1[kc * 4], b0.x, b0.y);
                hmma(d1[1], &A1[kc * 4], b0.z, b0.w);
                hmma(d1[2], &A1[kc * 4], b1.x, b1.y);
                hmma(d1[3], &A1[kc * 4], b1.z, b1.w);
                hmma(d1[4], &A1[kc * 4], b2.x, b2.y);
                hmma(d1[5], &A1[kc * 4], b2.z, b2.w);
            }

            uint4 An0, An1;
            EPI(d0, xnA0, xnB0, hp0, jcl * 8, An0);
            EPI(d1, xnA1, xnB1, hp1, jcl * 8, An1);
            exq[(p * 32 + jc) * 32] = An0;
            exq[(p * 32 + 8 + jc) * 32] = An1;
        }
        asm volatile("bar.sync %0, 128;" :: "r"(1 + quad) : "memory");
        LOAD_A(p);
        iA0 = jA0; iB0 = jB0; iA1 = jA1; iB1 = jB1;
    }

    // output projection: sub covers 4 of 16 f's, both tiles
    float od0[4][4], od1[4][4];
    #pragma unroll
    for (int f = 0; f < 4; f++)
        #pragma unroll
        for (int q = 0; q < 4; q++) { od0[f][q] = 0.0f; od1[f][q] = 0.0f; }
    #pragma unroll
    for (int kc = 0; kc < 8; kc++) {
        const uint4* op = ((const uint4*)(Os + (kc * 32 + T) * 32)) + sub * 2;
        uint4 v0 = op[0], v1 = op[1];
        hmma(od0[0], &A0[kc * 4], v0.x, v0.y);
        hmma(od0[1], &A0[kc * 4], v0.z, v0.w);
        hmma(od0[2], &A0[kc * 4], v1.x, v1.y);
        hmma(od0[3], &A0[kc * 4], v1.z, v1.w);
        hmma(od1[0], &A1[kc * 4], v0.x, v0.y);
        hmma(od1[1], &A1[kc * 4], v0.z, v0.w);
        hmma(od1[2], &A1[kc * 4], v1.x, v1.y);
        hmma(od1[3], &A1[kc * 4], v1.z, v1.w);
    }
    const int q2 = (T & 3) * 2;
    #pragma unroll
    for (int f2 = 0; f2 < 4; f2++) {
        const int f = sub * 4 + f2;
        float2 bo = *(const float2*)(bout + f * 8 + q2);
        *(float2*)(out + (size_t)rA0 * OUTD + f * 8 + q2) =
            make_float2(od0[f2][0] + bo.x, od0[f2][1] + bo.y);
        *(float2*)(out + (size_t)rB0 * OUTD + f * 8 + q2) =
            make_float2(od0[f2][2] + bo.x, od0[f2][3] + bo.y);
        *(float2*)(out + (size_t)rA1 * OUTD + f * 8 + q2) =
            make_float2(od1[f2][0] + bo.x, od1[f2][1] + bo.y);
        *(float2*)(out + (size_t)rB1 * OUTD + f * 8 + q2) =
            make_float2(od1[f2][2] + bo.x, od1[f2][3] + bo.y);
    }
}

extern "C" void kernel_launch(void* const* d_in, const int* in_sizes, int n_in,
                              void* d_out, int out_size) {
    const int*   x     = (const int*)d_in[0];
    const float* embed = (const float*)d_in[1];
    const float* Wih   = (const float*)d_in[2];
    const float* Whh   = (const float*)d_in[3];
    const float* bih   = (const float*)d_in[4];
    const float* bhh   = (const float*)d_in[5];
    const float* Wout  = (const float*)d_in[6];
    const float* bout  = (const float*)d_in[7];
    float* out = (float*)d_out;

    static bool attr_done = false;
    if (!attr_done) {
        cudaFuncSetAttribute(gru_kernel, cudaFuncAttributeMaxDynamicSharedMemorySize, GRU_SMEM);
        attr_done = true;
    }

    prep_kernel<<<192, 256>>>(Wih, Whh, bih, bhh, Wout);
    table_kernel<<<NVAL, G3>>>(embed);
    gru_kernel<<<B_SZ / 64, NTH, GRU_SMEM>>>(x, bhh, bout, out);
}